// round 1
// baseline (speedup 1.0000x reference)
#include <cuda_runtime.h>
#include <cuda_bf16.h>
#include <math.h>

// Problem constants (fixed for this dataset)
constexpr int L  = 4;
constexpr int D  = 64;
constexpr int H  = 8;
constexpr int HD = 512;        // H*D
constexpr int G3 = 3 * HD;     // 1536
constexpr int MAXE = 100000;
constexpr int NF   = 20000;
constexpr int NN   = 20000;

// Scratch (static device globals — no allocation allowed)
__device__ float g_GI[(size_t)NF * G3];     // gi = feat@Wih.T + b_ih  (122.9 MB, ~L2 resident)
__device__ float g_H1[(size_t)NF * HD];     // h after GRU step 1 per feature
__device__ float g_hA[(size_t)MAXE * HD];   // ping
__device__ float g_hB[(size_t)MAXE * HD];   // pong (final hidden ends here)
__device__ float g_a[(size_t)MAXE * H];     // attention logits -> exp values
__device__ float g_amax[(size_t)NN * H];
__device__ float g_denom[(size_t)NN * H];

__device__ __forceinline__ float sigmoidf_(float x) { return 1.0f / (1.0f + expf(-x)); }

__device__ __forceinline__ void atomicMaxF(float* addr, float v) {
    int old = __float_as_int(*addr);
    while (__int_as_float(old) < v) {
        int prev = atomicCAS((int*)addr, old, __float_as_int(v));
        if (prev == old) break;
        old = prev;
    }
}

// ---------------------------------------------------------------------------
// init: zero output, init segment-softmax accumulators
// ---------------------------------------------------------------------------
__global__ void init_kernel(float* __restrict__ out, int outN) {
    int i = blockIdx.x * blockDim.x + threadIdx.x;
    if (i < outN) out[i] = 0.0f;
    if (i < NN * H) { g_amax[i] = -3.0e38f; g_denom[i] = 0.0f; }
}

// ---------------------------------------------------------------------------
// GI = features @ w_ih.T + b_ih      [NF, 1536], K = 64
// tile: 16 f x 96 c per 256-thread block
// ---------------------------------------------------------------------------
__global__ void gi_kernel(const float* __restrict__ feat,
                          const float* __restrict__ w_ih,
                          const float* __restrict__ b_ih, int nf) {
    __shared__ float sF[16][D + 1];
    __shared__ float sW[96][D + 1];
    int f0 = blockIdx.x * 16;
    int c0 = blockIdx.y * 96;
    int tid = threadIdx.x;

    for (int i = tid; i < 16 * D; i += 256) {
        int r = i / D, k = i % D;
        int f = f0 + r;
        sF[r][k] = (f < nf) ? feat[(size_t)f * D + k] : 0.0f;
    }
    for (int i = tid; i < 96 * D; i += 256) {
        int r = i / D, k = i % D;
        sW[r][k] = w_ih[(size_t)(c0 + r) * D + k];
    }
    __syncthreads();

    int tx = tid & 31;   // c: tx, tx+32, tx+64
    int ty = tid >> 5;   // f: ty, ty+8
    float acc[2][3] = {};
#pragma unroll
    for (int k = 0; k < D; k++) {
        float a0 = sF[ty][k], a1 = sF[ty + 8][k];
        float b0 = sW[tx][k], b1 = sW[tx + 32][k], b2 = sW[tx + 64][k];
        acc[0][0] += a0 * b0; acc[0][1] += a0 * b1; acc[0][2] += a0 * b2;
        acc[1][0] += a1 * b0; acc[1][1] += a1 * b1; acc[1][2] += a1 * b2;
    }
#pragma unroll
    for (int i = 0; i < 2; i++) {
        int f = f0 + ty + i * 8;
        if (f >= nf) continue;
#pragma unroll
        for (int j = 0; j < 3; j++) {
            int c = c0 + tx + j * 32;
            g_GI[(size_t)f * G3 + c] = acc[i][j] + b_ih[c];
        }
    }
}

// ---------------------------------------------------------------------------
// H1 per feature: GRU step with h0 = 0  (gh == b_hh)
// ---------------------------------------------------------------------------
__global__ void h1_kernel(const float* __restrict__ b_hh, int nf) {
    int i = blockIdx.x * blockDim.x + threadIdx.x;
    if (i >= nf * HD) return;
    int f = i / HD, j = i % HD;
    const float* gi = g_GI + (size_t)f * G3;
    float r = sigmoidf_(gi[j] + b_hh[j]);
    float z = sigmoidf_(gi[HD + j] + b_hh[HD + j]);
    float n = tanhf(gi[2 * HD + j] + r * b_hh[2 * HD + j]);
    g_H1[i] = (1.0f - z) * n;
}

// ---------------------------------------------------------------------------
// h_cur[e] = H1[idx[e][0]]
// ---------------------------------------------------------------------------
__global__ void hinit_kernel(const int* __restrict__ mpi, int Ee) {
    int i = blockIdx.x * blockDim.x + threadIdx.x;
    if (i >= Ee * HD) return;
    int e = i / HD, j = i % HD;
    g_hA[i] = g_H1[(size_t)mpi[(size_t)e * L] * HD + j];
}

// ---------------------------------------------------------------------------
// Fused GRU step: gh = h_in @ w_hh.T (+b_hh), gate nonlinearity, h update
// Output tile: 128 edges x 32 j (each j has 3 gate accumulators)
// ---------------------------------------------------------------------------
__global__ __launch_bounds__(256, 2)
void gru_step_kernel(const int* __restrict__ mpi,
                     const float* __restrict__ w_hh,
                     const float* __restrict__ b_hh,
                     int Ee, int t, int srcSel) {
    const float* __restrict__ h_in  = srcSel ? g_hB : g_hA;
    float* __restrict__       h_out = srcSel ? g_hA : g_hB;

    __shared__ float sA[128][33];  // [e][k]
    __shared__ float sB[96][33];   // [g*32+j][k]

    int e0 = blockIdx.x * 128;
    int j0 = blockIdx.y * 32;
    int tid = threadIdx.x;
    int tx = tid & 15;   // j slots: tx, tx+16
    int ty = tid >> 4;   // e rows: ty*8 .. ty*8+7

    float acc[8][2][3] = {};   // [row][jslot][gate]

    for (int kb = 0; kb < HD; kb += 32) {
        for (int i = tid; i < 128 * 32; i += 256) {
            int r = i >> 5, k = i & 31;
            int e = e0 + r;
            sA[r][k] = (e < Ee) ? h_in[(size_t)e * HD + kb + k] : 0.0f;
        }
        for (int i = tid; i < 96 * 32; i += 256) {
            int rr = i >> 5, k = i & 31;
            int g = rr >> 5, j = rr & 31;
            sB[rr][k] = w_hh[(size_t)(g * HD + j0 + j) * HD + kb + k];
        }
        __syncthreads();
#pragma unroll
        for (int k = 0; k < 32; k++) {
            float a[8];
#pragma unroll
            for (int r = 0; r < 8; r++) a[r] = sA[ty * 8 + r][k];
            float b[2][3];
#pragma unroll
            for (int jj = 0; jj < 2; jj++)
#pragma unroll
                for (int g = 0; g < 3; g++)
                    b[jj][g] = sB[g * 32 + tx + jj * 16][k];
#pragma unroll
            for (int r = 0; r < 8; r++)
#pragma unroll
                for (int jj = 0; jj < 2; jj++)
#pragma unroll
                    for (int g = 0; g < 3; g++)
                        acc[r][jj][g] += a[r] * b[jj][g];
        }
        __syncthreads();
    }

    // Fused GRU-cell epilogue
#pragma unroll
    for (int jj = 0; jj < 2; jj++) {
        int j = j0 + tx + jj * 16;
        float br = b_hh[j], bz = b_hh[HD + j], bn = b_hh[2 * HD + j];
#pragma unroll
        for (int r = 0; r < 8; r++) {
            int e = e0 + ty * 8 + r;
            if (e >= Ee) continue;
            int f = mpi[(size_t)e * L + t];
            const float* gi = g_GI + (size_t)f * G3;
            float rg  = sigmoidf_(acc[r][jj][0] + br + gi[j]);
            float zg  = sigmoidf_(acc[r][jj][1] + bz + gi[HD + j]);
            float hn  = acc[r][jj][2] + bn;
            float ng  = tanhf(gi[2 * HD + j] + rg * hn);
            float ho  = h_in[(size_t)e * HD + j];
            h_out[(size_t)e * HD + j] = (1.0f - zg) * ng + zg * ho;
        }
    }
}

// ---------------------------------------------------------------------------
// attention logits + segment max (one warp per edge, all 8 heads)
// final hidden lives in g_hB
// ---------------------------------------------------------------------------
__global__ void attn_logits_kernel(const float* __restrict__ attn,
                                   const int* __restrict__ dst, int Ee) {
    __shared__ float sAttn[H * D];
    int tid = threadIdx.x;
    for (int i = tid; i < H * D; i += blockDim.x) sAttn[i] = attn[i];
    __syncthreads();
    int warp = tid >> 5, lane = tid & 31;
    int e = blockIdx.x * 8 + warp;
    if (e >= Ee) return;
    const float* hf = g_hB + (size_t)e * HD;
    int dn = dst[e];
#pragma unroll
    for (int h = 0; h < H; h++) {
        float v = hf[h * D + lane]      * sAttn[h * D + lane]
                + hf[h * D + 32 + lane] * sAttn[h * D + 32 + lane];
#pragma unroll
        for (int o = 16; o > 0; o >>= 1) v += __shfl_down_sync(0xffffffff, v, o);
        if (lane == 0) {
            float x = v > 0.0f ? v : 0.001f * v;   // leaky relu
            g_a[(size_t)e * H + h] = x;
            atomicMaxF(&g_amax[(size_t)dn * H + h], x);
        }
    }
}

__global__ void attn_exp_kernel(const int* __restrict__ dst, int Ee) {
    int i = blockIdx.x * blockDim.x + threadIdx.x;
    if (i >= Ee * H) return;
    int e = i / H, h = i - e * H;
    int dn = dst[e];
    float v = expf(g_a[i] - g_amax[(size_t)dn * H + h]);
    g_a[i] = v;
    atomicAdd(&g_denom[(size_t)dn * H + h], v);
}

__global__ void scatter_kernel(const int* __restrict__ dst,
                               float* __restrict__ out, int Ee) {
    int i = blockIdx.x * blockDim.x + threadIdx.x;
    if (i >= Ee * HD) return;
    int e = i / HD, c = i - e * HD;
    int h = c >> 6;
    int dn = dst[e];
    float att = g_a[(size_t)e * H + h] / fmaxf(g_denom[(size_t)dn * H + h], 1e-12f);
    atomicAdd(out + (size_t)dn * HD + c, g_hB[i] * att);
}

// ---------------------------------------------------------------------------
extern "C" void kernel_launch(void* const* d_in, const int* in_sizes, int n_in,
                              void* d_out, int out_size) {
    // input order: features, edge_metapath_indices, dst, [num_nodes], w_ih, w_hh, b_ih, b_hh, attn
    int off = (n_in >= 9) ? 1 : 0;
    const float* feat = (const float*)d_in[0];
    const int*   mpi  = (const int*)d_in[1];
    const int*   dst  = (const int*)d_in[2];
    const float* w_ih = (const float*)d_in[3 + off];
    const float* w_hh = (const float*)d_in[4 + off];
    const float* b_ih = (const float*)d_in[5 + off];
    const float* b_hh = (const float*)d_in[6 + off];
    const float* attn = (const float*)d_in[7 + off];
    float* out = (float*)d_out;

    int E  = in_sizes[2];
    int nf = in_sizes[0] / D;

    int initN = out_size > NN * H ? out_size : NN * H;
    init_kernel<<<(initN + 255) / 256, 256>>>(out, out_size);

    dim3 gi_grid((nf + 15) / 16, G3 / 96);
    gi_kernel<<<gi_grid, 256>>>(feat, w_ih, b_ih, nf);

    h1_kernel<<<(nf * HD + 255) / 256, 256>>>(b_hh, nf);
    hinit_kernel<<<(E * HD + 255) / 256, 256>>>(mpi, E);

    dim3 gru_grid((E + 127) / 128, HD / 32);
    // step t=1: A -> B ; t=2: B -> A ; t=3: A -> B  (final hidden in g_hB)
    gru_step_kernel<<<gru_grid, 256>>>(mpi, w_hh, b_hh, E, 1, 0);
    gru_step_kernel<<<gru_grid, 256>>>(mpi, w_hh, b_hh, E, 2, 1);
    gru_step_kernel<<<gru_grid, 256>>>(mpi, w_hh, b_hh, E, 3, 0);

    attn_logits_kernel<<<(E + 7) / 8, 256>>>(attn, dst, E);
    attn_exp_kernel<<<(E * H + 255) / 256, 256>>>(dst, E);
    scatter_kernel<<<(E * HD + 255) / 256, 256>>>(dst, out, E);
}

// round 3
// speedup vs baseline: 3.6970x; 3.6970x over previous
#include <cuda_runtime.h>
#include <cuda_bf16.h>
#include <math.h>
#include <stdint.h>

// Problem constants
constexpr int L  = 4;
constexpr int D  = 64;
constexpr int H  = 8;
constexpr int HD = 512;
constexpr int G3 = 3 * HD;     // 1536
constexpr int MAXE = 100000;
constexpr int NF   = 20000;
constexpr int NN   = 20000;

// ---------------- device scratch (no allocation allowed) ----------------
__device__ float g_GI[(size_t)NF * G3];                  // gi = feat@Wih.T + b_ih
__device__ float g_H1[(size_t)NF * HD];                  // h after GRU step 1 per feature
__device__ __nv_bfloat16 g_hAhi[(size_t)MAXE * HD];
__device__ __nv_bfloat16 g_hAlo[(size_t)MAXE * HD];
__device__ __nv_bfloat16 g_hBhi[(size_t)MAXE * HD];
__device__ __nv_bfloat16 g_hBlo[(size_t)MAXE * HD];
__device__ __nv_bfloat16 g_whi[(size_t)G3 * HD];
__device__ __nv_bfloat16 g_wlo[(size_t)G3 * HD];
__device__ float g_a[(size_t)MAXE * H];
__device__ float g_amax[(size_t)NN * H];
__device__ float g_denom[(size_t)NN * H];

// ---------------- fast math ----------------
__device__ __forceinline__ float fsig(float x)  { return __fdividef(1.0f, 1.0f + __expf(-x)); }
__device__ __forceinline__ float ftanh(float x) { float t = __expf(2.0f * x); return 1.0f - __fdividef(2.0f, t + 1.0f); }

__device__ __forceinline__ void atomicMaxF(float* addr, float v) {
    int old = __float_as_int(*addr);
    while (__int_as_float(old) < v) {
        int prev = atomicCAS((int*)addr, old, __float_as_int(v));
        if (prev == old) break;
        old = prev;
    }
}

// ---------------- PTX helpers (all plain sm_80+ features) ----------------
__device__ __forceinline__ uint32_t smem_u32(const void* p) {
    uint32_t a;
    asm("{ .reg .u64 t; cvta.to.shared.u64 t, %1; cvt.u32.u64 %0, t; }" : "=r"(a) : "l"(p));
    return a;
}
__device__ __forceinline__ void cpasync16(uint32_t dst, const void* src, int bytes) {
    asm volatile("cp.async.ca.shared.global [%0], [%1], 16, %2;" :: "r"(dst), "l"(src), "r"(bytes));
}
__device__ __forceinline__ void cpcommit() { asm volatile("cp.async.commit_group;" ::: "memory"); }
template<int N>
__device__ __forceinline__ void cpwait() { asm volatile("cp.async.wait_group %0;" :: "n"(N) : "memory"); }

__device__ __forceinline__ void ldsm4(uint32_t* r, uint32_t addr) {
    asm volatile("ldmatrix.sync.aligned.m8n8.x4.shared.b16 {%0,%1,%2,%3}, [%4];"
        : "=r"(r[0]), "=r"(r[1]), "=r"(r[2]), "=r"(r[3]) : "r"(addr));
}
__device__ __forceinline__ void mma16816(float* c, const uint32_t* a, uint32_t b0, uint32_t b1) {
    asm volatile("mma.sync.aligned.m16n8k16.row.col.f32.bf16.bf16.f32 "
        "{%0,%1,%2,%3}, {%4,%5,%6,%7}, {%8,%9}, {%0,%1,%2,%3};"
        : "+f"(c[0]), "+f"(c[1]), "+f"(c[2]), "+f"(c[3])
        : "r"(a[0]), "r"(a[1]), "r"(a[2]), "r"(a[3]), "r"(b0), "r"(b1));
}

// Swizzled tile: [R rows][64 bf16], row = 128B, chunk = 16B octet of bf16
__device__ __forceinline__ uint32_t toff(int r, int ch) {
    return (uint32_t)r * 128u + (uint32_t)((ch ^ (r & 7)) * 16);
}

// SMEM layout
constexpr uint32_t SM_BHH   = 0;        // 192 floats (768B), pad to 1024
constexpr uint32_t SM_STAGE = 1024;
constexpr uint32_t ST_AHI = 0;
constexpr uint32_t ST_ALO = 16384;      // 128x64 bf16
constexpr uint32_t ST_BHI = 32768;      // 192x64 bf16
constexpr uint32_t ST_BLO = 57344;
constexpr uint32_t STAGE_BYTES = 81920;
constexpr uint32_t SMEM_TOTAL = SM_STAGE + 2 * STAGE_BYTES;   // 164864

// ---------------------------------------------------------------------------
// init
// ---------------------------------------------------------------------------
__global__ void init_kernel(float* __restrict__ out, int outN) {
    int i = blockIdx.x * blockDim.x + threadIdx.x;
    if (i < outN) out[i] = 0.0f;
    if (i < NN * H) { g_amax[i] = -3.0e38f; g_denom[i] = 0.0f; }
}

// ---------------------------------------------------------------------------
// GI = features @ w_ih.T + b_ih   [NF, 1536], K=64
// ---------------------------------------------------------------------------
__global__ void gi_kernel(const float* __restrict__ feat,
                          const float* __restrict__ w_ih,
                          const float* __restrict__ b_ih, int nf) {
    __shared__ float sF[16][D + 1];
    __shared__ float sW[96][D + 1];
    int f0 = blockIdx.x * 16;
    int c0 = blockIdx.y * 96;
    int tid = threadIdx.x;

    for (int i = tid; i < 16 * D; i += 256) {
        int r = i / D, k = i % D;
        int f = f0 + r;
        sF[r][k] = (f < nf) ? feat[(size_t)f * D + k] : 0.0f;
    }
    for (int i = tid; i < 96 * D; i += 256) {
        int r = i / D, k = i % D;
        sW[r][k] = w_ih[(size_t)(c0 + r) * D + k];
    }
    __syncthreads();

    int tx = tid & 31;
    int ty = tid >> 5;
    float acc[2][3] = {};
#pragma unroll
    for (int k = 0; k < D; k++) {
        float a0 = sF[ty][k], a1 = sF[ty + 8][k];
        float b0 = sW[tx][k], b1 = sW[tx + 32][k], b2 = sW[tx + 64][k];
        acc[0][0] += a0 * b0; acc[0][1] += a0 * b1; acc[0][2] += a0 * b2;
        acc[1][0] += a1 * b0; acc[1][1] += a1 * b1; acc[1][2] += a1 * b2;
    }
#pragma unroll
    for (int i = 0; i < 2; i++) {
        int f = f0 + ty + i * 8;
        if (f >= nf) continue;
#pragma unroll
        for (int j = 0; j < 3; j++) {
            int c = c0 + tx + j * 32;
            g_GI[(size_t)f * G3 + c] = acc[i][j] + b_ih[c];
        }
    }
}

// ---------------------------------------------------------------------------
// split w_hh into bf16 hi/lo
// ---------------------------------------------------------------------------
__global__ void split_w_kernel(const float* __restrict__ w_hh) {
    int i = blockIdx.x * blockDim.x + threadIdx.x;
    if (i >= G3 * HD) return;
    float w = w_hh[i];
    __nv_bfloat16 hi = __float2bfloat16(w);
    g_whi[i] = hi;
    g_wlo[i] = __float2bfloat16(w - __bfloat162float(hi));
}

// ---------------------------------------------------------------------------
// H1 per feature (GRU step with h0=0 -> gh == b_hh)
// ---------------------------------------------------------------------------
__global__ void h1_kernel(const float* __restrict__ b_hh, int nf) {
    int i = blockIdx.x * blockDim.x + threadIdx.x;
    if (i >= nf * HD) return;
    int f = i / HD, j = i % HD;
    const float* gi = g_GI + (size_t)f * G3;
    float r = fsig(gi[j] + b_hh[j]);
    float z = fsig(gi[HD + j] + b_hh[HD + j]);
    float n = ftanh(gi[2 * HD + j] + r * b_hh[2 * HD + j]);
    g_H1[i] = (1.0f - z) * n;
}

// ---------------------------------------------------------------------------
// h_cur[e] = H1[mpi[e][0]]  -> split hi/lo into A buffers
// ---------------------------------------------------------------------------
__global__ void hinit_kernel(const int* __restrict__ mpi, int Ee) {
    int i = blockIdx.x * blockDim.x + threadIdx.x;
    if (i >= Ee * HD) return;
    int e = i / HD, j = i % HD;
    float h = g_H1[(size_t)mpi[(size_t)e * L] * HD + j];
    __nv_bfloat16 hi = __float2bfloat16(h);
    g_hAhi[i] = hi;
    g_hAlo[i] = __float2bfloat16(h - __bfloat162float(hi));
}

// ---------------------------------------------------------------------------
// GRU step via warp-level mma.sync (bf16 split: hi*hi + hi*lo + lo*hi)
// Grid: (ceil(E/128), 8). Block 256 = 8 warps.
// Warp w: e rows [esub*32, +32), j cols [j0w, +32); all 3 gates warp-local.
// ---------------------------------------------------------------------------
__global__ void __launch_bounds__(256, 1)
gru_mma_kernel(const int* __restrict__ mpi,
               const float* __restrict__ b_hh,
               int Ee, int t, int srcSel) {
    extern __shared__ char smem[];
    uint32_t sb = smem_u32(smem);
    int tid = threadIdx.x;
    int wid = tid >> 5;
    int lane = tid & 31;
    int esub = wid & 3;
    int j0w  = (wid >> 2) * 32;

    const __nv_bfloat16* __restrict__ Ahi = srcSel ? g_hBhi : g_hAhi;
    const __nv_bfloat16* __restrict__ Alo = srcSel ? g_hBlo : g_hAlo;
    __nv_bfloat16* __restrict__ Ohi = srcSel ? g_hAhi : g_hBhi;
    __nv_bfloat16* __restrict__ Olo = srcSel ? g_hAlo : g_hBlo;

    int e0 = blockIdx.x * 128;
    int j0g = blockIdx.y * 64;

    // bias slice for this CTA's j-block
    float* s_bhh = (float*)(smem + SM_BHH);
    for (int i = tid; i < 192; i += 256)
        s_bhh[i] = b_hh[(i >> 6) * HD + j0g + (i & 63)];

    // chunk loader (cp.async)
    auto load_chunk = [&](int kc, int s) {
        uint32_t base = sb + SM_STAGE + (uint32_t)s * STAGE_BYTES;
        int k0 = kc * 64;
#pragma unroll
        for (int it = 0; it < 4; it++) {
            int idx = tid + it * 256;          // 0..1023
            int row = idx >> 3, ch = idx & 7;
            int e = e0 + row;
            int ec = e < Ee ? e : 0;
            int bytes = (e < Ee) ? 16 : 0;
            size_t go = (size_t)ec * HD + k0 + ch * 8;
            uint32_t so = toff(row, ch);
            cpasync16(base + ST_AHI + so, Ahi + go, bytes);
            cpasync16(base + ST_ALO + so, Alo + go, bytes);
        }
#pragma unroll
        for (int it = 0; it < 6; it++) {
            int idx = tid + it * 256;          // 0..1535
            int row = idx >> 3, ch = idx & 7;
            size_t go = ((size_t)((row >> 6) * HD + j0g + (row & 63))) * HD + k0 + ch * 8;
            uint32_t so = toff(row, ch);
            cpasync16(base + ST_BHI + so, g_whi + go, 16);
            cpasync16(base + ST_BLO + so, g_wlo + go, 16);
        }
        cpcommit();
    };

    float acc[3][2][4][4];
#pragma unroll
    for (int g = 0; g < 3; g++)
#pragma unroll
        for (int mi = 0; mi < 2; mi++)
#pragma unroll
            for (int ni = 0; ni < 4; ni++)
#pragma unroll
                for (int c = 0; c < 4; c++) acc[g][mi][ni][c] = 0.0f;

    load_chunk(0, 0);

    for (int kc = 0; kc < 8; kc++) {
        if (kc < 7) { load_chunk(kc + 1, (kc + 1) & 1); cpwait<1>(); }
        else        { cpwait<0>(); }
        __syncthreads();

        uint32_t base = sb + SM_STAGE + (uint32_t)(kc & 1) * STAGE_BYTES;
#pragma unroll
        for (int ks = 0; ks < 4; ks++) {
            // A fragments (hi and lo): 2 m-tiles of 16 rows
            uint32_t ah[2][4], al[2][4];
#pragma unroll
            for (int mi = 0; mi < 2; mi++) {
                int r  = esub * 32 + mi * 16 + (lane & 15);
                int ch = ks * 2 + (lane >> 4);
                uint32_t so = toff(r, ch);
                ldsm4(ah[mi], base + ST_AHI + so);
                ldsm4(al[mi], base + ST_ALO + so);
            }
#pragma unroll
            for (int g = 0; g < 3; g++) {
                uint32_t bh[2][4], bl[2][4];
#pragma unroll
                for (int p = 0; p < 2; p++) {
                    int r  = g * 64 + j0w + p * 16 + ((lane >> 4) << 3) + (lane & 7);
                    int ch = ks * 2 + ((lane >> 3) & 1);
                    uint32_t so = toff(r, ch);
                    ldsm4(bh[p], base + ST_BHI + so);
                    ldsm4(bl[p], base + ST_BLO + so);
                }
#pragma unroll
                for (int mi = 0; mi < 2; mi++)
#pragma unroll
                    for (int p = 0; p < 2; p++)
#pragma unroll
                        for (int q = 0; q < 2; q++) {
                            float* c = acc[g][mi][p * 2 + q];
                            mma16816(c, ah[mi], bh[p][q * 2], bh[p][q * 2 + 1]);
                            mma16816(c, ah[mi], bl[p][q * 2], bl[p][q * 2 + 1]);
                            mma16816(c, al[mi], bh[p][q * 2], bh[p][q * 2 + 1]);
                        }
            }
        }
        __syncthreads();
    }

    // -------- fused GRU cell epilogue (all warp-local) --------
#pragma unroll
    for (int mi = 0; mi < 2; mi++) {
#pragma unroll
        for (int rh = 0; rh < 2; rh++) {
            int e = e0 + esub * 32 + mi * 16 + rh * 8 + (lane >> 2);
            if (e >= Ee) continue;
            int f = mpi[(size_t)e * L + t];
            const float* giRow = g_GI + (size_t)f * G3;
#pragma unroll
            for (int ni = 0; ni < 4; ni++) {
                int jl = j0w + ni * 8 + (lane & 3) * 2;
                int j  = j0g + jl;
                float gr0 = acc[0][mi][ni][rh * 2], gr1 = acc[0][mi][ni][rh * 2 + 1];
                float gz0 = acc[1][mi][ni][rh * 2], gz1 = acc[1][mi][ni][rh * 2 + 1];
                float gn0 = acc[2][mi][ni][rh * 2], gn1 = acc[2][mi][ni][rh * 2 + 1];
                float2 ir = *(const float2*)(giRow + j);
                float2 iz = *(const float2*)(giRow + HD + j);
                float2 in = *(const float2*)(giRow + 2 * HD + j);
                float r0 = fsig(gr0 + s_bhh[jl]       + ir.x);
                float r1 = fsig(gr1 + s_bhh[jl + 1]   + ir.y);
                float z0 = fsig(gz0 + s_bhh[64 + jl]     + iz.x);
                float z1 = fsig(gz1 + s_bhh[64 + jl + 1] + iz.y);
                float n0 = ftanh(in.x + r0 * (gn0 + s_bhh[128 + jl]));
                float n1 = ftanh(in.y + r1 * (gn1 + s_bhh[128 + jl + 1]));
                __nv_bfloat162 hp_hi = *(const __nv_bfloat162*)(Ahi + (size_t)e * HD + j);
                __nv_bfloat162 hp_lo = *(const __nv_bfloat162*)(Alo + (size_t)e * HD + j);
                float h0 = (1.0f - z0) * n0 + z0 * (__bfloat162float(hp_hi.x) + __bfloat162float(hp_lo.x));
                float h1 = (1.0f - z1) * n1 + z1 * (__bfloat162float(hp_hi.y) + __bfloat162float(hp_lo.y));
                __nv_bfloat16 o0 = __float2bfloat16(h0);
                __nv_bfloat16 o1 = __float2bfloat16(h1);
                __nv_bfloat162 ohi; ohi.x = o0; ohi.y = o1;
                __nv_bfloat162 olo;
                olo.x = __float2bfloat16(h0 - __bfloat162float(o0));
                olo.y = __float2bfloat16(h1 - __bfloat162float(o1));
                *(__nv_bfloat162*)(Ohi + (size_t)e * HD + j) = ohi;
                *(__nv_bfloat162*)(Olo + (size_t)e * HD + j) = olo;
            }
        }
    }
}

// ---------------------------------------------------------------------------
// attention logits + segment max (final hidden in g_hB hi/lo)
// ---------------------------------------------------------------------------
__global__ void attn_logits_kernel(const float* __restrict__ attn,
                                   const int* __restrict__ dst, int Ee) {
    __shared__ float sAttn[H * D];
    int tid = threadIdx.x;
    for (int i = tid; i < H * D; i += blockDim.x) sAttn[i] = attn[i];
    __syncthreads();
    int warp = tid >> 5, lane = tid & 31;
    int e = blockIdx.x * 8 + warp;
    if (e >= Ee) return;
    const __nv_bfloat16* hh = g_hBhi + (size_t)e * HD;
    const __nv_bfloat16* hl = g_hBlo + (size_t)e * HD;
    int dn = dst[e];
#pragma unroll
    for (int h = 0; h < H; h++) {
        int i0 = h * D + lane, i1 = h * D + 32 + lane;
        float v = (__bfloat162float(hh[i0]) + __bfloat162float(hl[i0])) * sAttn[i0]
                + (__bfloat162float(hh[i1]) + __bfloat162float(hl[i1])) * sAttn[i1];
#pragma unroll
        for (int o = 16; o > 0; o >>= 1) v += __shfl_down_sync(0xffffffff, v, o);
        if (lane == 0) {
            float x = v > 0.0f ? v : 0.001f * v;
            g_a[(size_t)e * H + h] = x;
            atomicMaxF(&g_amax[(size_t)dn * H + h], x);
        }
    }
}

__global__ void attn_exp_kernel(const int* __restrict__ dst, int Ee) {
    int i = blockIdx.x * blockDim.x + threadIdx.x;
    if (i >= Ee * H) return;
    int e = i / H, h = i - e * H;
    int dn = dst[e];
    float v = expf(g_a[i] - g_amax[(size_t)dn * H + h]);
    g_a[i] = v;
    atomicAdd(&g_denom[(size_t)dn * H + h], v);
}

__global__ void scatter_kernel(const int* __restrict__ dst,
                               float* __restrict__ out, int Ee) {
    int i = blockIdx.x * blockDim.x + threadIdx.x;
    if (i >= Ee * HD) return;
    int e = i / HD, c = i - e * HD;
    int h = c >> 6;
    int dn = dst[e];
    float att = g_a[(size_t)e * H + h] / fmaxf(g_denom[(size_t)dn * H + h], 1e-12f);
    float hv = __bfloat162float(g_hBhi[i]) + __bfloat162float(g_hBlo[i]);
    atomicAdd(out + (size_t)dn * HD + c, hv * att);
}

// ---------------------------------------------------------------------------
extern "C" void kernel_launch(void* const* d_in, const int* in_sizes, int n_in,
                              void* d_out, int out_size) {
    int off = (n_in >= 9) ? 1 : 0;
    const float* feat = (const float*)d_in[0];
    const int*   mpi  = (const int*)d_in[1];
    const int*   dst  = (const int*)d_in[2];
    const float* w_ih = (const float*)d_in[3 + off];
    const float* w_hh = (const float*)d_in[4 + off];
    const float* b_ih = (const float*)d_in[5 + off];
    const float* b_hh = (const float*)d_in[6 + off];
    const float* attn = (const float*)d_in[7 + off];
    float* out = (float*)d_out;

    int E  = in_sizes[2];
    int nf = in_sizes[0] / D;

    cudaFuncSetAttribute(gru_mma_kernel, cudaFuncAttributeMaxDynamicSharedMemorySize, SMEM_TOTAL);

    int initN = out_size > NN * H ? out_size : NN * H;
    init_kernel<<<(initN + 255) / 256, 256>>>(out, out_size);

    dim3 gi_grid((nf + 15) / 16, G3 / 96);
    gi_kernel<<<gi_grid, 256>>>(feat, w_ih, b_ih, nf);

    split_w_kernel<<<(G3 * HD + 255) / 256, 256>>>(w_hh);
    h1_kernel<<<(nf * HD + 255) / 256, 256>>>(b_hh, nf);
    hinit_kernel<<<(E * HD + 255) / 256, 256>>>(mpi, E);

    dim3 gru_grid((E + 127) / 128, HD / 64);
    // t=1: A->B ; t=2: B->A ; t=3: A->B  (final hidden in g_hB)
    gru_mma_kernel<<<gru_grid, 256, SMEM_TOTAL>>>(mpi, b_hh, E, 1, 0);
    gru_mma_kernel<<<gru_grid, 256, SMEM_TOTAL>>>(mpi, b_hh, E, 2, 1);
    gru_mma_kernel<<<gru_grid, 256, SMEM_TOTAL>>>(mpi, b_hh, E, 3, 0);

    attn_logits_kernel<<<(E + 7) / 8, 256>>>(attn, dst, E);
    attn_exp_kernel<<<(E * H + 255) / 256, 256>>>(dst, E);
    scatter_kernel<<<(E * HD + 255) / 256, 256>>>(dst, out, E);
}

// round 4
// speedup vs baseline: 6.1558x; 1.6651x over previous
#include <cuda_runtime.h>
#include <cuda_fp16.h>
#include <math.h>
#include <stdint.h>

// Problem constants
constexpr int L  = 4;
constexpr int D  = 64;
constexpr int H  = 8;
constexpr int HD = 512;
constexpr int G3 = 3 * HD;     // 1536
constexpr int MAXE = 100000;
constexpr int NF   = 20000;
constexpr int NN   = 20000;

// ---------------- device scratch ----------------
__device__ float g_GI[(size_t)NF * G3];     // gi = feat@Wih.T + b_ih (fp32, exact)
__device__ float g_H1[(size_t)NF * HD];     // h after GRU step 1 per feature
__device__ __half g_hA[(size_t)MAXE * HD];  // ping (fp16 hidden)
__device__ __half g_hB[(size_t)MAXE * HD];  // pong (final hidden ends here)
__device__ __half g_w[(size_t)G3 * HD];     // w_hh in fp16
__device__ float g_a[(size_t)MAXE * H];
__device__ float g_amax[(size_t)NN * H];
__device__ float g_denom[(size_t)NN * H];

// ---------------- fast math ----------------
__device__ __forceinline__ float fsig(float x)  { return __fdividef(1.0f, 1.0f + __expf(-x)); }
__device__ __forceinline__ float ftanh(float x) { float t = __expf(2.0f * x); return 1.0f - __fdividef(2.0f, t + 1.0f); }

__device__ __forceinline__ void atomicMaxF(float* addr, float v) {
    int old = __float_as_int(*addr);
    while (__int_as_float(old) < v) {
        int prev = atomicCAS((int*)addr, old, __float_as_int(v));
        if (prev == old) break;
        old = prev;
    }
}

// ---------------- PTX helpers (plain sm_80+) ----------------
__device__ __forceinline__ uint32_t smem_u32(const void* p) {
    uint32_t a;
    asm("{ .reg .u64 t; cvta.to.shared.u64 t, %1; cvt.u32.u64 %0, t; }" : "=r"(a) : "l"(p));
    return a;
}
__device__ __forceinline__ void cpasync16(uint32_t dst, const void* src, int bytes) {
    asm volatile("cp.async.ca.shared.global [%0], [%1], 16, %2;" :: "r"(dst), "l"(src), "r"(bytes));
}
__device__ __forceinline__ void cpcommit() { asm volatile("cp.async.commit_group;" ::: "memory"); }
template<int N>
__device__ __forceinline__ void cpwait() { asm volatile("cp.async.wait_group %0;" :: "n"(N) : "memory"); }

__device__ __forceinline__ void ldsm4(uint32_t* r, uint32_t addr) {
    asm volatile("ldmatrix.sync.aligned.m8n8.x4.shared.b16 {%0,%1,%2,%3}, [%4];"
        : "=r"(r[0]), "=r"(r[1]), "=r"(r[2]), "=r"(r[3]) : "r"(addr));
}
__device__ __forceinline__ void mma16816(float* c, const uint32_t* a, uint32_t b0, uint32_t b1) {
    asm volatile("mma.sync.aligned.m16n8k16.row.col.f32.f16.f16.f32 "
        "{%0,%1,%2,%3}, {%4,%5,%6,%7}, {%8,%9}, {%0,%1,%2,%3};"
        : "+f"(c[0]), "+f"(c[1]), "+f"(c[2]), "+f"(c[3])
        : "r"(a[0]), "r"(a[1]), "r"(a[2]), "r"(a[3]), "r"(b0), "r"(b1));
}

// Swizzled tile: [R rows][64 fp16], row = 128B, ch = 16B octet
__device__ __forceinline__ uint32_t toff(int r, int ch) {
    return (uint32_t)r * 128u + (uint32_t)((ch ^ (r & 7)) * 16);
}

// SMEM layout
constexpr uint32_t SM_BHH   = 0;        // 192 floats, pad to 1024
constexpr uint32_t SM_STAGE = 1024;
constexpr uint32_t ST_A = 0;            // 128x64 fp16 = 16KB
constexpr uint32_t ST_B = 16384;        // 192x64 fp16 = 24KB
constexpr uint32_t STAGE_BYTES = 40960;
constexpr uint32_t SMEM_TOTAL = SM_STAGE + 2 * STAGE_BYTES;   // 82944

// ---------------------------------------------------------------------------
__global__ void init_kernel(float* __restrict__ out, int outN) {
    int i = blockIdx.x * blockDim.x + threadIdx.x;
    if (i < outN) out[i] = 0.0f;
    if (i < NN * H) { g_amax[i] = -3.0e38f; g_denom[i] = 0.0f; }
}

// ---------------------------------------------------------------------------
// GI = features @ w_ih.T + b_ih   [NF, 1536], K=64  (fp32 exact)
// ---------------------------------------------------------------------------
__global__ void gi_kernel(const float* __restrict__ feat,
                          const float* __restrict__ w_ih,
                          const float* __restrict__ b_ih, int nf) {
    __shared__ float sF[16][D + 1];
    __shared__ float sW[96][D + 1];
    int f0 = blockIdx.x * 16;
    int c0 = blockIdx.y * 96;
    int tid = threadIdx.x;

    for (int i = tid; i < 16 * D; i += 256) {
        int r = i / D, k = i % D;
        int f = f0 + r;
        sF[r][k] = (f < nf) ? feat[(size_t)f * D + k] : 0.0f;
    }
    for (int i = tid; i < 96 * D; i += 256) {
        int r = i / D, k = i % D;
        sW[r][k] = w_ih[(size_t)(c0 + r) * D + k];
    }
    __syncthreads();

    int tx = tid & 31;
    int ty = tid >> 5;
    float acc[2][3] = {};
#pragma unroll
    for (int k = 0; k < D; k++) {
        float a0 = sF[ty][k], a1 = sF[ty + 8][k];
        float b0 = sW[tx][k], b1 = sW[tx + 32][k], b2 = sW[tx + 64][k];
        acc[0][0] += a0 * b0; acc[0][1] += a0 * b1; acc[0][2] += a0 * b2;
        acc[1][0] += a1 * b0; acc[1][1] += a1 * b1; acc[1][2] += a1 * b2;
    }
#pragma unroll
    for (int i = 0; i < 2; i++) {
        int f = f0 + ty + i * 8;
        if (f >= nf) continue;
#pragma unroll
        for (int j = 0; j < 3; j++) {
            int c = c0 + tx + j * 32;
            g_GI[(size_t)f * G3 + c] = acc[i][j] + b_ih[c];
        }
    }
}

// ---------------------------------------------------------------------------
__global__ void convert_w_kernel(const float* __restrict__ w_hh) {
    int i = blockIdx.x * blockDim.x + threadIdx.x;
    if (i >= G3 * HD) return;
    g_w[i] = __float2half(w_hh[i]);
}

// ---------------------------------------------------------------------------
__global__ void h1_kernel(const float* __restrict__ b_hh, int nf) {
    int i = blockIdx.x * blockDim.x + threadIdx.x;
    if (i >= nf * HD) return;
    int f = i / HD, j = i % HD;
    const float* gi = g_GI + (size_t)f * G3;
    float r = fsig(gi[j] + b_hh[j]);
    float z = fsig(gi[HD + j] + b_hh[HD + j]);
    float n = ftanh(gi[2 * HD + j] + r * b_hh[2 * HD + j]);
    g_H1[i] = (1.0f - z) * n;
}

// ---------------------------------------------------------------------------
__global__ void hinit_kernel(const int* __restrict__ mpi, int Ee) {
    int i = blockIdx.x * blockDim.x + threadIdx.x;
    if (i >= Ee * HD) return;
    int e = i / HD, j = i % HD;
    g_hA[i] = __float2half(g_H1[(size_t)mpi[(size_t)e * L] * HD + j]);
}

// ---------------------------------------------------------------------------
// GRU step via warp-level mma.sync, fp16 operands, fp32 accum.
// Grid: (ceil(E/128), 8). Block 256 = 8 warps.
// Warp w: e rows [esub*32,+32), j cols [j0w,+32); 3 gates warp-local.
// ---------------------------------------------------------------------------
__global__ void __launch_bounds__(256, 1)
gru_mma_kernel(const int* __restrict__ mpi,
               const float* __restrict__ b_hh,
               int Ee, int t, int srcSel) {
    extern __shared__ char smem[];
    uint32_t sb = smem_u32(smem);
    int tid = threadIdx.x;
    int wid = tid >> 5;
    int lane = tid & 31;
    int esub = wid & 3;
    int j0w  = (wid >> 2) * 32;

    const __half* __restrict__ A = srcSel ? g_hB : g_hA;
    __half* __restrict__       O = srcSel ? g_hA : g_hB;

    int e0 = blockIdx.x * 128;
    int j0g = blockIdx.y * 64;

    float* s_bhh = (float*)(smem + SM_BHH);
    for (int i = tid; i < 192; i += 256)
        s_bhh[i] = b_hh[(i >> 6) * HD + j0g + (i & 63)];

    auto load_chunk = [&](int kc, int s) {
        uint32_t base = sb + SM_STAGE + (uint32_t)s * STAGE_BYTES;
        int k0 = kc * 64;
#pragma unroll
        for (int it = 0; it < 4; it++) {
            int idx = tid + it * 256;          // 0..1023
            int row = idx >> 3, ch = idx & 7;
            int e = e0 + row;
            int ec = e < Ee ? e : 0;
            int bytes = (e < Ee) ? 16 : 0;
            cpasync16(base + ST_A + toff(row, ch), A + (size_t)ec * HD + k0 + ch * 8, bytes);
        }
#pragma unroll
        for (int it = 0; it < 6; it++) {
            int idx = tid + it * 256;          // 0..1535
            int row = idx >> 3, ch = idx & 7;
            size_t go = ((size_t)((row >> 6) * HD + j0g + (row & 63))) * HD + k0 + ch * 8;
            cpasync16(base + ST_B + toff(row, ch), g_w + go, 16);
        }
        cpcommit();
    };

    float acc[3][2][4][4];
#pragma unroll
    for (int g = 0; g < 3; g++)
#pragma unroll
        for (int mi = 0; mi < 2; mi++)
#pragma unroll
            for (int ni = 0; ni < 4; ni++)
#pragma unroll
                for (int c = 0; c < 4; c++) acc[g][mi][ni][c] = 0.0f;

    load_chunk(0, 0);

    for (int kc = 0; kc < 8; kc++) {
        if (kc < 7) { load_chunk(kc + 1, (kc + 1) & 1); cpwait<1>(); }
        else        { cpwait<0>(); }
        __syncthreads();

        uint32_t base = sb + SM_STAGE + (uint32_t)(kc & 1) * STAGE_BYTES;
#pragma unroll
        for (int ks = 0; ks < 4; ks++) {
            uint32_t a[2][4];
#pragma unroll
            for (int mi = 0; mi < 2; mi++) {
                int r  = esub * 32 + mi * 16 + (lane & 15);
                int ch = ks * 2 + (lane >> 4);
                ldsm4(a[mi], base + ST_A + toff(r, ch));
            }
#pragma unroll
            for (int g = 0; g < 3; g++) {
                uint32_t b[2][4];
#pragma unroll
                for (int p = 0; p < 2; p++) {
                    int r  = g * 64 + j0w + p * 16 + ((lane >> 4) << 3) + (lane & 7);
                    int ch = ks * 2 + ((lane >> 3) & 1);
                    ldsm4(b[p], base + ST_B + toff(r, ch));
                }
#pragma unroll
                for (int mi = 0; mi < 2; mi++)
#pragma unroll
                    for (int p = 0; p < 2; p++)
#pragma unroll
                        for (int q = 0; q < 2; q++)
                            mma16816(acc[g][mi][p * 2 + q], a[mi], b[p][q * 2], b[p][q * 2 + 1]);
            }
        }
        __syncthreads();
    }

    // -------- fused GRU cell epilogue (warp-local) --------
#pragma unroll
    for (int mi = 0; mi < 2; mi++) {
#pragma unroll
        for (int rh = 0; rh < 2; rh++) {
            int e = e0 + esub * 32 + mi * 16 + rh * 8 + (lane >> 2);
            if (e >= Ee) continue;
            int f = mpi[(size_t)e * L + t];
            const float* giRow = g_GI + (size_t)f * G3;
#pragma unroll
            for (int ni = 0; ni < 4; ni++) {
                int jl = j0w + ni * 8 + (lane & 3) * 2;
                int j  = j0g + jl;
                float gr0 = acc[0][mi][ni][rh * 2], gr1 = acc[0][mi][ni][rh * 2 + 1];
                float gz0 = acc[1][mi][ni][rh * 2], gz1 = acc[1][mi][ni][rh * 2 + 1];
                float gn0 = acc[2][mi][ni][rh * 2], gn1 = acc[2][mi][ni][rh * 2 + 1];
                float2 ir = *(const float2*)(giRow + j);
                float2 iz = *(const float2*)(giRow + HD + j);
                float2 in = *(const float2*)(giRow + 2 * HD + j);
                float r0 = fsig(gr0 + s_bhh[jl]          + ir.x);
                float r1 = fsig(gr1 + s_bhh[jl + 1]      + ir.y);
                float z0 = fsig(gz0 + s_bhh[64 + jl]     + iz.x);
                float z1 = fsig(gz1 + s_bhh[64 + jl + 1] + iz.y);
                float n0 = ftanh(in.x + r0 * (gn0 + s_bhh[128 + jl]));
                float n1 = ftanh(in.y + r1 * (gn1 + s_bhh[128 + jl + 1]));
                __half2 hp = *(const __half2*)(A + (size_t)e * HD + j);
                float h0 = (1.0f - z0) * n0 + z0 * __half2float(hp.x);
                float h1 = (1.0f - z1) * n1 + z1 * __half2float(hp.y);
                __half2 oh;
                oh.x = __float2half(h0);
                oh.y = __float2half(h1);
                *(__half2*)(O + (size_t)e * HD + j) = oh;
            }
        }
    }
}

// ---------------------------------------------------------------------------
__global__ void attn_logits_kernel(const float* __restrict__ attn,
                                   const int* __restrict__ dst, int Ee) {
    __shared__ float sAttn[H * D];
    int tid = threadIdx.x;
    for (int i = tid; i < H * D; i += blockDim.x) sAttn[i] = attn[i];
    __syncthreads();
    int warp = tid >> 5, lane = tid & 31;
    int e = blockIdx.x * 8 + warp;
    if (e >= Ee) return;
    const __half* hf = g_hB + (size_t)e * HD;
    int dn = dst[e];
#pragma unroll
    for (int h = 0; h < H; h++) {
        int i0 = h * D + lane, i1 = h * D + 32 + lane;
        float v = __half2float(hf[i0]) * sAttn[i0] + __half2float(hf[i1]) * sAttn[i1];
#pragma unroll
        for (int o = 16; o > 0; o >>= 1) v += __shfl_down_sync(0xffffffff, v, o);
        if (lane == 0) {
            float x = v > 0.0f ? v : 0.001f * v;
            g_a[(size_t)e * H + h] = x;
            atomicMaxF(&g_amax[(size_t)dn * H + h], x);
        }
    }
}

__global__ void attn_exp_kernel(const int* __restrict__ dst, int Ee) {
    int i = blockIdx.x * blockDim.x + threadIdx.x;
    if (i >= Ee * H) return;
    int e = i / H, h = i - e * H;
    int dn = dst[e];
    float v = expf(g_a[i] - g_amax[(size_t)dn * H + h]);
    g_a[i] = v;
    atomicAdd(&g_denom[(size_t)dn * H + h], v);
}

__global__ void scatter_kernel(const int* __restrict__ dst,
                               float* __restrict__ out, int Ee) {
    int i = blockIdx.x * blockDim.x + threadIdx.x;
    if (i >= Ee * HD) return;
    int e = i / HD, c = i - e * HD;
    int h = c >> 6;
    int dn = dst[e];
    float att = g_a[(size_t)e * H + h] / fmaxf(g_denom[(size_t)dn * H + h], 1e-12f);
    atomicAdd(out + (size_t)dn * HD + c, __half2float(g_hB[i]) * att);
}

// ---------------------------------------------------------------------------
extern "C" void kernel_launch(void* const* d_in, const int* in_sizes, int n_in,
                              void* d_out, int out_size) {
    int off = (n_in >= 9) ? 1 : 0;
    const float* feat = (const float*)d_in[0];
    const int*   mpi  = (const int*)d_in[1];
    const int*   dst  = (const int*)d_in[2];
    const float* w_ih = (const float*)d_in[3 + off];
    const float* w_hh = (const float*)d_in[4 + off];
    const float* b_ih = (const float*)d_in[5 + off];
    const float* b_hh = (const float*)d_in[6 + off];
    const float* attn = (const float*)d_in[7 + off];
    float* out = (float*)d_out;

    int E  = in_sizes[2];
    int nf = in_sizes[0] / D;

    cudaFuncSetAttribute(gru_mma_kernel, cudaFuncAttributeMaxDynamicSharedMemorySize, SMEM_TOTAL);

    int initN = out_size > NN * H ? out_size : NN * H;
    init_kernel<<<(initN + 255) / 256, 256>>>(out, out_size);

    dim3 gi_grid((nf + 15) / 16, G3 / 96);
    gi_kernel<<<gi_grid, 256>>>(feat, w_ih, b_ih, nf);

    convert_w_kernel<<<(G3 * HD + 255) / 256, 256>>>(w_hh);
    h1_kernel<<<(nf * HD + 255) / 256, 256>>>(b_hh, nf);
    hinit_kernel<<<(E * HD + 255) / 256, 256>>>(mpi, E);

    dim3 gru_grid((E + 127) / 128, HD / 64);
    // t=1: A->B ; t=2: B->A ; t=3: A->B  (final hidden in g_hB)
    gru_mma_kernel<<<gru_grid, 256, SMEM_TOTAL>>>(mpi, b_hh, E, 1, 0);
    gru_mma_kernel<<<gru_grid, 256, SMEM_TOTAL>>>(mpi, b_hh, E, 2, 1);
    gru_mma_kernel<<<gru_grid, 256, SMEM_TOTAL>>>(mpi, b_hh, E, 3, 0);

    attn_logits_kernel<<<(E + 7) / 8, 256>>>(attn, dst, E);
    attn_exp_kernel<<<(E * H + 255) / 256, 256>>>(dst, E);
    scatter_kernel<<<(E * HD + 255) / 256, 256>>>(dst, out, E);
}

// round 5
// speedup vs baseline: 6.7360x; 1.0943x over previous
#include <cuda_runtime.h>
#include <cuda_fp16.h>
#include <math.h>
#include <stdint.h>

// Problem constants
constexpr int L  = 4;
constexpr int D  = 64;
constexpr int H  = 8;
constexpr int HD = 512;
constexpr int G3 = 3 * HD;     // 1536
constexpr int MAXE = 100000;
constexpr int NF   = 20000;
constexpr int NN   = 20000;

// ---------------- device scratch ----------------
__device__ float g_GI[(size_t)NF * G3];      // gi = feat@Wih.T + b_ih (fp32, exact)
__device__ __half g_H1h[(size_t)NF * HD];    // h after GRU step 1 per feature (fp16)
__device__ __half g_hA[(size_t)MAXE * HD];   // ping
__device__ __half g_hB[(size_t)MAXE * HD];   // pong (final hidden ends here)
__device__ __half g_w[(size_t)G3 * HD];      // w_hh in fp16
__device__ float g_a[(size_t)MAXE * H];
__device__ float g_amax[(size_t)NN * H];
__device__ float g_denom[(size_t)NN * H];

// ---------------- fast math ----------------
__device__ __forceinline__ float fsig(float x)  { return __fdividef(1.0f, 1.0f + __expf(-x)); }
__device__ __forceinline__ float ftanh(float x) { float t = __expf(2.0f * x); return 1.0f - __fdividef(2.0f, t + 1.0f); }

__device__ __forceinline__ void atomicMaxF(float* addr, float v) {
    int old = __float_as_int(*addr);
    while (__int_as_float(old) < v) {
        int prev = atomicCAS((int*)addr, old, __float_as_int(v));
        if (prev == old) break;
        old = prev;
    }
}

// ---------------- PTX helpers (plain sm_80+) ----------------
__device__ __forceinline__ uint32_t smem_u32(const void* p) {
    uint32_t a;
    asm("{ .reg .u64 t; cvta.to.shared.u64 t, %1; cvt.u32.u64 %0, t; }" : "=r"(a) : "l"(p));
    return a;
}
__device__ __forceinline__ void cpasync16(uint32_t dst, const void* src, int bytes) {
    asm volatile("cp.async.ca.shared.global [%0], [%1], 16, %2;" :: "r"(dst), "l"(src), "r"(bytes));
}
__device__ __forceinline__ void cpcommit() { asm volatile("cp.async.commit_group;" ::: "memory"); }
template<int N>
__device__ __forceinline__ void cpwait() { asm volatile("cp.async.wait_group %0;" :: "n"(N) : "memory"); }

__device__ __forceinline__ void ldsm4(uint32_t* r, uint32_t addr) {
    asm volatile("ldmatrix.sync.aligned.m8n8.x4.shared.b16 {%0,%1,%2,%3}, [%4];"
        : "=r"(r[0]), "=r"(r[1]), "=r"(r[2]), "=r"(r[3]) : "r"(addr));
}
__device__ __forceinline__ void mma16816(float* c, const uint32_t* a, uint32_t b0, uint32_t b1) {
    asm volatile("mma.sync.aligned.m16n8k16.row.col.f32.f16.f16.f32 "
        "{%0,%1,%2,%3}, {%4,%5,%6,%7}, {%8,%9}, {%0,%1,%2,%3};"
        : "+f"(c[0]), "+f"(c[1]), "+f"(c[2]), "+f"(c[3])
        : "r"(a[0]), "r"(a[1]), "r"(a[2]), "r"(a[3]), "r"(b0), "r"(b1));
}

// Swizzled tile: [R rows][64 fp16], row = 128B, ch = 16B octet
__device__ __forceinline__ uint32_t toff(int r, int ch) {
    return (uint32_t)r * 128u + (uint32_t)((ch ^ (r & 7)) * 16);
}

// SMEM layout: 3-stage pipeline
constexpr uint32_t SM_BHH   = 0;
constexpr uint32_t SM_STAGE = 1024;
constexpr uint32_t ST_A = 0;            // 128x64 fp16 = 16KB
constexpr uint32_t ST_B = 16384;        // 192x64 fp16 = 24KB
constexpr uint32_t STAGE_BYTES = 40960;
constexpr uint32_t SMEM_TOTAL = SM_STAGE + 3 * STAGE_BYTES;   // 123904

// ---------------------------------------------------------------------------
__global__ void init_kernel(float* __restrict__ out, int outN) {
    int i = blockIdx.x * blockDim.x + threadIdx.x;
    if (i < outN) out[i] = 0.0f;
    if (i < NN * H) { g_amax[i] = -3.0e38f; g_denom[i] = 0.0f; }
}

// ---------------------------------------------------------------------------
// GI = features @ w_ih.T + b_ih   [NF, 1536], K=64  (fp32 exact)
// tile 32f x 96c, 12 accumulators/thread
// ---------------------------------------------------------------------------
__global__ void gi_kernel(const float* __restrict__ feat,
                          const float* __restrict__ w_ih,
                          const float* __restrict__ b_ih, int nf) {
    __shared__ float sF[32][D + 1];
    __shared__ float sW[96][D + 1];
    int f0 = blockIdx.x * 32;
    int c0 = blockIdx.y * 96;
    int tid = threadIdx.x;

    for (int i = tid; i < 32 * D; i += 256) {
        int r = i >> 6, k = i & 63;
        int f = f0 + r;
        sF[r][k] = (f < nf) ? feat[(size_t)f * D + k] : 0.0f;
    }
    for (int i = tid; i < 96 * D; i += 256) {
        int r = i >> 6, k = i & 63;
        sW[r][k] = w_ih[(size_t)(c0 + r) * D + k];
    }
    __syncthreads();

    int tx = tid & 31;   // c: tx, tx+32, tx+64
    int ty = tid >> 5;   // f: ty, ty+8, ty+16, ty+24
    float acc[4][3] = {};
#pragma unroll
    for (int k = 0; k < D; k++) {
        float a0 = sF[ty][k], a1 = sF[ty + 8][k], a2 = sF[ty + 16][k], a3 = sF[ty + 24][k];
        float b0 = sW[tx][k], b1 = sW[tx + 32][k], b2 = sW[tx + 64][k];
        acc[0][0] += a0 * b0; acc[0][1] += a0 * b1; acc[0][2] += a0 * b2;
        acc[1][0] += a1 * b0; acc[1][1] += a1 * b1; acc[1][2] += a1 * b2;
        acc[2][0] += a2 * b0; acc[2][1] += a2 * b1; acc[2][2] += a2 * b2;
        acc[3][0] += a3 * b0; acc[3][1] += a3 * b1; acc[3][2] += a3 * b2;
    }
#pragma unroll
    for (int i = 0; i < 4; i++) {
        int f = f0 + ty + i * 8;
        if (f >= nf) continue;
#pragma unroll
        for (int j = 0; j < 3; j++) {
            int c = c0 + tx + j * 32;
            g_GI[(size_t)f * G3 + c] = acc[i][j] + b_ih[c];
        }
    }
}

// ---------------------------------------------------------------------------
__global__ void convert_w_kernel(const float* __restrict__ w_hh) {
    int i = blockIdx.x * blockDim.x + threadIdx.x;
    if (i >= G3 * HD) return;
    g_w[i] = __float2half(w_hh[i]);
}

// ---------------------------------------------------------------------------
// H1 per feature (GRU step with h0=0 -> gh == b_hh), stored fp16
// ---------------------------------------------------------------------------
__global__ void h1_kernel(const float* __restrict__ b_hh, int nf) {
    int i = blockIdx.x * blockDim.x + threadIdx.x;
    if (i >= nf * HD) return;
    int f = i / HD, j = i % HD;
    const float* gi = g_GI + (size_t)f * G3;
    float r = fsig(gi[j] + b_hh[j]);
    float z = fsig(gi[HD + j] + b_hh[HD + j]);
    float n = ftanh(gi[2 * HD + j] + r * b_hh[2 * HD + j]);
    g_H1h[i] = __float2half((1.0f - z) * n);
}

// ---------------------------------------------------------------------------
// GRU step via warp-level mma.sync (fp16), 3-stage cp.async pipeline.
// mode 0: A = H1h gathered by mpi[e][0], O = hB   (t = 1)
// mode 1: A = hB, O = hA                          (t = 2)
// mode 2: A = hA, O = hB                          (t = 3)
// ---------------------------------------------------------------------------
__global__ void __launch_bounds__(256, 1)
gru_mma_kernel(const int* __restrict__ mpi,
               const float* __restrict__ b_hh,
               int Ee, int t, int mode) {
    extern __shared__ char smem[];
    uint32_t sb = smem_u32(smem);
    int tid = threadIdx.x;
    int wid = tid >> 5;
    int lane = tid & 31;
    int esub = wid & 3;
    int j0w  = (wid >> 2) * 32;

    const __half* __restrict__ A = (mode == 0) ? g_H1h : (mode == 1 ? g_hB : g_hA);
    __half* __restrict__       O = (mode == 1) ? g_hA : g_hB;
    bool gather = (mode == 0);

    int e0 = blockIdx.x * 128;
    int j0g = blockIdx.y * 64;

    float* s_bhh = (float*)(smem + SM_BHH);
    for (int i = tid; i < 192; i += 256)
        s_bhh[i] = b_hh[(i >> 6) * HD + j0g + (i & 63)];

    // ---- hoisted per-thread load descriptors ----
    const __half* aPtr[4];
    uint32_t soA[4];
    int aBytes[4];
#pragma unroll
    for (int it = 0; it < 4; it++) {
        int idx = tid + it * 256;          // 0..1023
        int row = idx >> 3, ch = idx & 7;
        int e = e0 + row;
        bool v = e < Ee;
        int arow = v ? (gather ? mpi[(size_t)e * L] : e) : 0;
        aPtr[it] = A + (size_t)arow * HD + ch * 8;
        soA[it] = toff(row, ch);
        aBytes[it] = v ? 16 : 0;
    }
    const __half* bPtr[6];
    uint32_t soB[6];
#pragma unroll
    for (int it = 0; it < 6; it++) {
        int idx = tid + it * 256;          // 0..1535
        int row = idx >> 3, ch = idx & 7;
        bPtr[it] = g_w + (size_t)((row >> 6) * HD + j0g + (row & 63)) * HD + ch * 8;
        soB[it] = toff(row, ch);
    }

    auto load_chunk = [&](int kc, int s) {
        uint32_t base = sb + SM_STAGE + (uint32_t)s * STAGE_BYTES;
        int k0 = kc * 64;
#pragma unroll
        for (int it = 0; it < 4; it++)
            cpasync16(base + ST_A + soA[it], aPtr[it] + k0, aBytes[it]);
#pragma unroll
        for (int it = 0; it < 6; it++)
            cpasync16(base + ST_B + soB[it], bPtr[it] + k0, 16);
        cpcommit();
    };

    float acc[3][2][4][4];
#pragma unroll
    for (int g = 0; g < 3; g++)
#pragma unroll
        for (int mi = 0; mi < 2; mi++)
#pragma unroll
            for (int ni = 0; ni < 4; ni++)
#pragma unroll
                for (int c = 0; c < 4; c++) acc[g][mi][ni][c] = 0.0f;

    load_chunk(0, 0);
    load_chunk(1, 1);
    cpwait<1>();
    __syncthreads();

    for (int kc = 0; kc < 8; kc++) {
        if (kc + 2 < 8) load_chunk(kc + 2, (kc + 2) % 3);

        uint32_t base = sb + SM_STAGE + (uint32_t)(kc % 3) * STAGE_BYTES;
#pragma unroll
        for (int ks = 0; ks < 4; ks++) {
            uint32_t a[2][4];
#pragma unroll
            for (int mi = 0; mi < 2; mi++) {
                int r  = esub * 32 + mi * 16 + (lane & 15);
                int ch = ks * 2 + (lane >> 4);
                ldsm4(a[mi], base + ST_A + toff(r, ch));
            }
#pragma unroll
            for (int g = 0; g < 3; g++) {
                uint32_t b[2][4];
#pragma unroll
                for (int p = 0; p < 2; p++) {
                    int r  = g * 64 + j0w + p * 16 + ((lane >> 4) << 3) + (lane & 7);
                    int ch = ks * 2 + ((lane >> 3) & 1);
                    ldsm4(b[p], base + ST_B + toff(r, ch));
                }
#pragma unroll
                for (int mi = 0; mi < 2; mi++)
#pragma unroll
                    for (int p = 0; p < 2; p++)
#pragma unroll
                        for (int q = 0; q < 2; q++)
                            mma16816(acc[g][mi][p * 2 + q], a[mi], b[p][q * 2], b[p][q * 2 + 1]);
            }
        }
        if (kc < 7) {
            if (kc + 2 < 8) cpwait<1>(); else cpwait<0>();
            __syncthreads();
        }
    }

    // -------- fused GRU cell epilogue (warp-local) --------
#pragma unroll
    for (int mi = 0; mi < 2; mi++) {
#pragma unroll
        for (int rh = 0; rh < 2; rh++) {
            int e = e0 + esub * 32 + mi * 16 + rh * 8 + (lane >> 2);
            if (e >= Ee) continue;
            int f = mpi[(size_t)e * L + t];
            size_t arow = gather ? (size_t)mpi[(size_t)e * L] : (size_t)e;
            const float* giRow = g_GI + (size_t)f * G3;
#pragma unroll
            for (int ni = 0; ni < 4; ni++) {
                int jl = j0w + ni * 8 + (lane & 3) * 2;
                int j  = j0g + jl;
                float gr0 = acc[0][mi][ni][rh * 2], gr1 = acc[0][mi][ni][rh * 2 + 1];
                float gz0 = acc[1][mi][ni][rh * 2], gz1 = acc[1][mi][ni][rh * 2 + 1];
                float gn0 = acc[2][mi][ni][rh * 2], gn1 = acc[2][mi][ni][rh * 2 + 1];
                float2 ir = *(const float2*)(giRow + j);
                float2 iz = *(const float2*)(giRow + HD + j);
                float2 in = *(const float2*)(giRow + 2 * HD + j);
                float r0 = fsig(gr0 + s_bhh[jl]          + ir.x);
                float r1 = fsig(gr1 + s_bhh[jl + 1]      + ir.y);
                float z0 = fsig(gz0 + s_bhh[64 + jl]     + iz.x);
                float z1 = fsig(gz1 + s_bhh[64 + jl + 1] + iz.y);
                float n0 = ftanh(in.x + r0 * (gn0 + s_bhh[128 + jl]));
                float n1 = ftanh(in.y + r1 * (gn1 + s_bhh[128 + jl + 1]));
                __half2 hp = *(const __half2*)(A + arow * HD + j);
                float h0 = (1.0f - z0) * n0 + z0 * __half2float(hp.x);
                float h1 = (1.0f - z1) * n1 + z1 * __half2float(hp.y);
                __half2 oh;
                oh.x = __float2half(h0);
                oh.y = __float2half(h1);
                *(__half2*)(O + (size_t)e * HD + j) = oh;
            }
        }
    }
}

// ---------------------------------------------------------------------------
__global__ void attn_logits_kernel(const float* __restrict__ attn,
                                   const int* __restrict__ dst, int Ee) {
    __shared__ float sAttn[H * D];
    int tid = threadIdx.x;
    for (int i = tid; i < H * D; i += blockDim.x) sAttn[i] = attn[i];
    __syncthreads();
    int warp = tid >> 5, lane = tid & 31;
    int e = blockIdx.x * 8 + warp;
    if (e >= Ee) return;
    const __half* hf = g_hB + (size_t)e * HD;
    int dn = dst[e];
#pragma unroll
    for (int h = 0; h < H; h++) {
        int i0 = h * D + lane, i1 = h * D + 32 + lane;
        float v = __half2float(hf[i0]) * sAttn[i0] + __half2float(hf[i1]) * sAttn[i1];
#pragma unroll
        for (int o = 16; o > 0; o >>= 1) v += __shfl_down_sync(0xffffffff, v, o);
        if (lane == 0) {
            float x = v > 0.0f ? v : 0.001f * v;
            g_a[(size_t)e * H + h] = x;
            atomicMaxF(&g_amax[(size_t)dn * H + h], x);
        }
    }
}

__global__ void attn_exp_kernel(const int* __restrict__ dst, int Ee) {
    int i = blockIdx.x * blockDim.x + threadIdx.x;
    if (i >= Ee * H) return;
    int e = i / H, h = i - e * H;
    int dn = dst[e];
    float v = expf(g_a[i] - g_amax[(size_t)dn * H + h]);
    g_a[i] = v;
    atomicAdd(&g_denom[(size_t)dn * H + h], v);
}

__global__ void scatter_kernel(const int* __restrict__ dst,
                               float* __restrict__ out, int Ee) {
    int i = blockIdx.x * blockDim.x + threadIdx.x;
    if (i >= Ee * HD) return;
    int e = i / HD, c = i - e * HD;
    int h = c >> 6;
    int dn = dst[e];
    float att = g_a[(size_t)e * H + h] / fmaxf(g_denom[(size_t)dn * H + h], 1e-12f);
    atomicAdd(out + (size_t)dn * HD + c, __half2float(g_hB[i]) * att);
}

// ---------------------------------------------------------------------------
extern "C" void kernel_launch(void* const* d_in, const int* in_sizes, int n_in,
                              void* d_out, int out_size) {
    int off = (n_in >= 9) ? 1 : 0;
    const float* feat = (const float*)d_in[0];
    const int*   mpi  = (const int*)d_in[1];
    const int*   dst  = (const int*)d_in[2];
    const float* w_ih = (const float*)d_in[3 + off];
    const float* w_hh = (const float*)d_in[4 + off];
    const float* b_ih = (const float*)d_in[5 + off];
    const float* b_hh = (const float*)d_in[6 + off];
    const float* attn = (const float*)d_in[7 + off];
    float* out = (float*)d_out;

    int E  = in_sizes[2];
    int nf = in_sizes[0] / D;

    cudaFuncSetAttribute(gru_mma_kernel, cudaFuncAttributeMaxDynamicSharedMemorySize, SMEM_TOTAL);

    int initN = out_size > NN * H ? out_size : NN * H;
    init_kernel<<<(initN + 255) / 256, 256>>>(out, out_size);

    dim3 gi_grid((nf + 31) / 32, G3 / 96);
    gi_kernel<<<gi_grid, 256>>>(feat, w_ih, b_ih, nf);

    convert_w_kernel<<<(G3 * HD + 255) / 256, 256>>>(w_hh);
    h1_kernel<<<(nf * HD + 255) / 256, 256>>>(b_hh, nf);

    dim3 gru_grid((E + 127) / 128, HD / 64);
    gru_mma_kernel<<<gru_grid, 256, SMEM_TOTAL>>>(mpi, b_hh, E, 1, 0);  // H1h(gather) -> hB
    gru_mma_kernel<<<gru_grid, 256, SMEM_TOTAL>>>(mpi, b_hh, E, 2, 1);  // hB -> hA
    gru_mma_kernel<<<gru_grid, 256, SMEM_TOTAL>>>(mpi, b_hh, E, 3, 2);  // hA -> hB

    attn_logits_kernel<<<(E + 7) / 8, 256>>>(attn, dst, E);
    attn_exp_kernel<<<(E * H + 255) / 256, 256>>>(dst, E);
    scatter_kernel<<<(E * HD + 255) / 256, 256>>>(dst, out, E);
}